// round 1
// baseline (speedup 1.0000x reference)
#include <cuda_runtime.h>

#define B_TOT  8192
#define NN     82
#define HH     10
#define NOUT   5
#define TSTEPS 3
#define GB     4            // batches per block
#define BD     352          // 11 warps; active threads = 82*4 = 328
#define NROW   12           // padded floats per (node, g) row -> 48B, 16B aligned

// shared-memory float offsets
#define SM_ADJ   0                           // 2*NN*NN interleaved (in,out) pairs
#define SM_NODES (2*NN*NN)                   // NN*GB*NROW
#define SM_W3W   (SM_NODES + NN*GB*NROW)     // 200
#define SM_W4W   (SM_W3W + 200)              // 200
#define SM_W5W   (SM_W4W + 200)              // 200
#define SM_WOUT  (SM_W5W + 200)              // 100
#define SM_W3U   (SM_WOUT + 100)             // 120 (rows padded to 12)
#define SM_W5U   (SM_W3U + 120)              // 120
#define SM_BZ    (SM_W5U + 120)              // 16
#define SM_BR    (SM_BZ + 16)                // 16
#define SM_BH    (SM_BR + 16)                // 16
#define SM_BO    (SM_BH + 16)                // 16
#define SM_TOTAL (SM_BO + 16)

union F4U { float4 v; unsigned long long u[2]; };
union F2U { unsigned long long u; float2 f; };

__device__ __forceinline__ unsigned long long pack2(float a, float b) {
    unsigned long long r;
    asm("mov.b64 %0, {%1, %2};" : "=l"(r) : "f"(a), "f"(b));
    return r;
}
__device__ __forceinline__ void fma2(unsigned long long& acc,
                                     unsigned long long a, unsigned long long b) {
    asm("fma.rn.f32x2 %0, %1, %2, %0;" : "+l"(acc) : "l"(a), "l"(b));
}

__device__ __forceinline__ float sigmoid_f(float v) {
    return __fdividef(1.0f, 1.0f + __expf(-v));
}
__device__ __forceinline__ float tanh_f(float v) {
    return __fdividef(2.0f, 1.0f + __expf(-2.0f * v)) - 1.0f;
}

__global__ __launch_bounds__(BD, 2)
void ggnn_kernel(const float* __restrict__ x,
                 const float* __restrict__ in_adj,
                 const float* __restrict__ out_adj,
                 const float* __restrict__ w3w, const float* __restrict__ b3w,
                 const float* __restrict__ w3u, const float* __restrict__ b3u,
                 const float* __restrict__ w4w, const float* __restrict__ b4w,
                 const float* __restrict__ w5w, const float* __restrict__ b5w,
                 const float* __restrict__ w5u, const float* __restrict__ b5u,
                 const float* __restrict__ wout, const float* __restrict__ bout,
                 float* __restrict__ out0, float* __restrict__ outfn)
{
    extern __shared__ float sm[];
    const int tid = threadIdx.x;

    // ---- cooperative setup loads ----
    for (int idx = tid; idx < NN * NN; idx += BD) {
        sm[SM_ADJ + 2 * idx]     = in_adj[idx];
        sm[SM_ADJ + 2 * idx + 1] = out_adj[idx];
    }
    for (int idx = tid; idx < 200; idx += BD) {
        sm[SM_W3W + idx] = w3w[idx];
        sm[SM_W4W + idx] = w4w[idx];
        sm[SM_W5W + idx] = w5w[idx];
    }
    for (int idx = tid; idx < 100; idx += BD) {
        sm[SM_WOUT + idx] = wout[idx];
        int h = idx / 10, k = idx - 10 * h;
        sm[SM_W3U + h * 12 + k] = w3u[idx];
        sm[SM_W5U + h * 12 + k] = w5u[idx];
    }
    if (tid < HH) {
        sm[SM_BZ + tid] = b3w[tid] + b3u[tid];
        sm[SM_BR + tid] = b4w[tid] + b3u[tid];   // reference bug: r reuses b3u
        sm[SM_BH + tid] = b5w[tid] + b5u[tid];
    }
    if (tid < NOUT) sm[SM_BO + tid] = bout[tid];

    const int  i   = tid >> 2;       // node index
    const int  g   = tid & 3;        // batch-in-block
    const bool act = (tid < NN * GB);
    const int  b   = blockIdx.x * GB + g;

    float fn[HH];
    if (act) {
        const float* xr = x + ((size_t)b * NN + i) * HH;
        float* nr = sm + SM_NODES + (i * GB + g) * NROW;
        #pragma unroll
        for (int h = 0; h < HH; h++) { fn[h] = xr[h]; nr[h] = fn[h]; }
    }
    __syncthreads();

    for (int st = 0; st < TSTEPS; st++) {
        if (act) {
            // ---- aggregation: a_in/a_out = adj rows dot node states (f32x2 packed) ----
            unsigned long long acc[HH];   // [0..4]=a_in pairs, [5..9]=a_out pairs
            #pragma unroll
            for (int p = 0; p < HH; p++) acc[p] = 0ULL;

            const float* arow  = sm + SM_ADJ + i * (2 * NN);
            const float* nbase = sm + SM_NODES + g * NROW;
            #pragma unroll 2
            for (int j = 0; j < NN; j++) {
                F2U ab; ab.u = *(const unsigned long long*)(arow + 2 * j);
                unsigned long long aa = pack2(ab.f.x, ab.f.x);
                unsigned long long bb = pack2(ab.f.y, ab.f.y);
                const float* xr2 = nbase + j * (GB * NROW);
                F4U q0, q1; F2U q2;
                q0.v = *(const float4*)(xr2);
                q1.v = *(const float4*)(xr2 + 4);
                q2.f = *(const float2*)(xr2 + 8);
                fma2(acc[0], aa, q0.u[0]);  fma2(acc[5], bb, q0.u[0]);
                fma2(acc[1], aa, q0.u[1]);  fma2(acc[6], bb, q0.u[1]);
                fma2(acc[2], aa, q1.u[0]);  fma2(acc[7], bb, q1.u[0]);
                fma2(acc[3], aa, q1.u[1]);  fma2(acc[8], bb, q1.u[1]);
                fma2(acc[4], aa, q2.u);     fma2(acc[9], bb, q2.u);
            }

            float av[2 * HH];
            #pragma unroll
            for (int p = 0; p < 5; p++) {
                F2U u;
                u.u = acc[p];     av[2 * p] = u.f.x;      av[2 * p + 1] = u.f.y;
                u.u = acc[5 + p]; av[10 + 2 * p] = u.f.x; av[10 + 2 * p + 1] = u.f.y;
            }

            // ---- dense GRU-style gates ----
            float zv[HH], rv[HH];
            #pragma unroll
            for (int h = 0; h < HH; h++) {
                const float* u3r = sm + SM_W3U + h * 12;
                float u3 = 0.f;
                #pragma unroll
                for (int k = 0; k < HH; k++) u3 += u3r[k] * fn[k];
                float zp = sm[SM_BZ + h] + u3;
                float rp = sm[SM_BR + h] + u3;   // reference bug: r reuses w3u*fn
                const float* w3r = sm + SM_W3W + h * 20;
                const float* w4r = sm + SM_W4W + h * 20;
                #pragma unroll
                for (int k = 0; k < 20; k++) {
                    zp += w3r[k] * av[k];
                    rp += w4r[k] * av[k];
                }
                zv[h] = sigmoid_f(zp);
                rv[h] = sigmoid_f(rp);
            }
            #pragma unroll
            for (int h = 0; h < HH; h++) rv[h] *= fn[h];   // rv := rv * fn
            #pragma unroll
            for (int h = 0; h < HH; h++) {
                const float* w5r = sm + SM_W5W + h * 20;
                const float* u5r = sm + SM_W5U + h * 12;
                float hp = sm[SM_BH + h];
                #pragma unroll
                for (int k = 0; k < 20; k++) hp += w5r[k] * av[k];
                #pragma unroll
                for (int k = 0; k < HH; k++) hp += u5r[k] * rv[k];
                float hv = tanh_f(hp);
                fn[h] = fn[h] + zv[h] * (hv - fn[h]);      // (1-z)*fn + z*hv
            }
        }
        __syncthreads();   // all aggregation reads of s_nodes done
        if (act) {
            float* nr = sm + SM_NODES + (i * GB + g) * NROW;
            #pragma unroll
            for (int h = 0; h < HH; h++) nr[h] = fn[h];
        }
        __syncthreads();   // new states visible
    }

    // ---- output head: tanh(wout * [fn, x] + bout), plus fn itself ----
    if (act) {
        const float* xr = x + ((size_t)b * NN + i) * HH;
        float xo[HH];
        #pragma unroll
        for (int h = 0; h < HH; h++) xo[h] = xr[h];

        const size_t row = (size_t)b * NN + i;
        float* op = out0 + row * NOUT;
        #pragma unroll
        for (int o = 0; o < NOUT; o++) {
            const float* wr = sm + SM_WOUT + o * 20;
            float a0 = sm[SM_BO + o];
            #pragma unroll
            for (int k = 0; k < HH; k++) a0 += wr[k] * fn[k];
            #pragma unroll
            for (int k = 0; k < HH; k++) a0 += wr[10 + k] * xo[k];
            op[o] = tanh_f(a0);
        }
        float* fp = outfn + row * HH;
        #pragma unroll
        for (int h = 0; h < HH; h++) fp[h] = fn[h];
    }
}

extern "C" void kernel_launch(void* const* d_in, const int* in_sizes, int n_in,
                              void* d_out, int out_size)
{
    const float* x       = (const float*)d_in[0];
    const float* in_adj  = (const float*)d_in[1];
    const float* out_adj = (const float*)d_in[2];
    const float* w3w  = (const float*)d_in[3];
    const float* b3w  = (const float*)d_in[4];
    const float* w3u  = (const float*)d_in[5];
    const float* b3u  = (const float*)d_in[6];
    const float* w4w  = (const float*)d_in[7];
    const float* b4w  = (const float*)d_in[8];
    const float* w5w  = (const float*)d_in[9];
    const float* b5w  = (const float*)d_in[10];
    const float* w5u  = (const float*)d_in[11];
    const float* b5u  = (const float*)d_in[12];
    const float* wout = (const float*)d_in[13];
    const float* bout = (const float*)d_in[14];

    float* out0  = (float*)d_out;
    float* outfn = out0 + (size_t)B_TOT * NN * NOUT;

    const size_t smbytes = SM_TOTAL * sizeof(float);
    cudaFuncSetAttribute(ggnn_kernel,
                         cudaFuncAttributeMaxDynamicSharedMemorySize,
                         (int)smbytes);

    ggnn_kernel<<<B_TOT / GB, BD, smbytes>>>(
        x, in_adj, out_adj,
        w3w, b3w, w3u, b3u, w4w, b4w, w5w, b5w, w5u, b5u, wout, bout,
        out0, outfn);
}